// round 1
// baseline (speedup 1.0000x reference)
#include <cuda_runtime.h>

// ---------------- problem constants ----------------
#define BT     8
#define NPIX   4096          // 64*64
#define DD     512
#define CFF    128
#define INCC   640
#define GG     64            // windows per image
#define NWIN   64            // tokens per window
#define NGLOB  64            // global tokens per image
#define NHEAD  8
#define DHH    64
#define MTOK   32768         // BT*NPIX

// ---------------- scratch (__device__ globals; no runtime alloc) ----------------
__device__ float g_qk [BT*NPIX*INCC];      // reweighted concat(x,f), spatial layout
__device__ float g_kg [BT*NGLOB*INCC];     // dwconv(qk)
__device__ float g_vg [BT*NGLOB*DD];       // dwconv(x)
__device__ float g_Q  [BT*GG*NWIN*DD];     // windowed layout
__device__ float g_Kl [BT*GG*NWIN*DD];
__device__ float g_Vl [BT*GG*NWIN*DD];
__device__ float g_Kg [BT*NGLOB*DD];
__device__ float g_Vg [BT*NGLOB*DD];
__device__ float g_O  [BT*GG*NWIN*DD];     // attention output, windowed
__device__ float g_st_qk[MTOK*2];
__device__ float g_st_x [MTOK*2];
__device__ float g_st_kg[BT*NGLOB*2];
__device__ float g_st_vg[BT*NGLOB*2];

// spatial row -> windowed row
__device__ __forceinline__ int win_map(int r) {
    int b = r >> 12;
    int p = r & 4095;
    int h = p >> 6, w = p & 63;
    int g = ((h >> 3) << 3) | (w >> 3);
    int n = ((h & 7) << 3) | (w & 7);
    return (((b << 6) | g) << 6) | n;
}

// ---------------- LayerNorm row stats ----------------
__global__ __launch_bounds__(256)
void ln_stats_kernel(const float* __restrict__ X, float* __restrict__ stats, int K) {
    int row = blockIdx.x;
    const float* xr = X + (size_t)row * K;
    float s = 0.f, ss = 0.f;
    for (int k = threadIdx.x; k < K; k += 256) {
        float v = xr[k];
        s += v; ss += v * v;
    }
    #pragma unroll
    for (int o = 16; o; o >>= 1) {
        s  += __shfl_xor_sync(0xffffffffu, s, o);
        ss += __shfl_xor_sync(0xffffffffu, ss, o);
    }
    __shared__ float sm[8], sm2[8];
    int w = threadIdx.x >> 5, l = threadIdx.x & 31;
    if (l == 0) { sm[w] = s; sm2[w] = ss; }
    __syncthreads();
    if (threadIdx.x == 0) {
        float S = 0.f, SS = 0.f;
        #pragma unroll
        for (int i = 0; i < 8; i++) { S += sm[i]; SS += sm2[i]; }
        float mean = S / K;
        float var = SS / K - mean * mean;
        stats[row * 2]     = mean;
        stats[row * 2 + 1] = rsqrtf(var + 1e-5f);
    }
}

// ---------------- depthwise 8x8 stride-8 conv ----------------
__global__ __launch_bounds__(256)
void dwconv_kernel(const float* __restrict__ X, const float* __restrict__ Wc,
                   const float* __restrict__ bc, float* __restrict__ out, int C) {
    int bw = blockIdx.x;          // b*64 + g
    int b = bw >> 6;
    int g = bw & 63;
    int gh = g >> 3, gw = g & 7;
    const float* xb = X + (size_t)b * NPIX * C;
    for (int c = threadIdx.x; c < C; c += 256) {
        float s = bc[c];
        #pragma unroll
        for (int i = 0; i < 8; i++) {
            #pragma unroll
            for (int j = 0; j < 8; j++) {
                s += xb[(size_t)((gh * 8 + i) * 64 + (gw * 8 + j)) * C + c]
                     * Wc[c * 64 + i * 8 + j];
            }
        }
        out[(size_t)bw * C + c] = s;
    }
}

// ---------------- generic tiled GEMM: C[M,N] = op(A)[M,K] @ W[N,K]^T ----------------
// MODE 0: A = concat(x,f); epilogue: out = a_elem * sigmoid(acc+bias); write spatial (g_qk)
// MODE 1: A with fused LN (stats,gamma,beta); epilogue +bias; output row = win_map (windowed)
// MODE 2: as MODE 1 but output row identity (global K/V rows)
// MODE 3: A row gathered via win_map (windowed->spatial reverse); epilogue +bias; output spatial
template<int MODE>
__global__ __launch_bounds__(256)
void gemm_kernel(const float* __restrict__ A, const float* __restrict__ A2,
                 const float* __restrict__ W, const float* __restrict__ bias,
                 const float* __restrict__ stats, const float* __restrict__ gamma,
                 const float* __restrict__ beta,
                 float* __restrict__ C, int M, int N, int K) {
    __shared__ __align__(16) float As[16][68];
    __shared__ __align__(16) float Bs[16][68];
    const int m0 = blockIdx.y * 64;
    const int n0 = blockIdx.x * 64;
    const int tid = threadIdx.x;
    const int ty = tid >> 4, tx = tid & 15;
    const int arow = tid >> 2;            // 0..63
    const int akb  = (tid & 3) << 2;      // 0,4,8,12

    float mean = 0.f, rstd = 0.f;
    if (MODE == 1 || MODE == 2) {
        mean = stats[(m0 + arow) * 2];
        rstd = stats[(m0 + arow) * 2 + 1];
    }
    int a_in_row = (MODE == 3) ? win_map(m0 + arow) : (m0 + arow);

    float acc[4][4];
    #pragma unroll
    for (int i = 0; i < 4; i++)
        #pragma unroll
        for (int j = 0; j < 4; j++) acc[i][j] = 0.f;

    for (int k0 = 0; k0 < K; k0 += 16) {
        int gk = k0 + akb;
        float4 av;
        if (MODE == 0) {
            if (gk < 512) av = *(const float4*)(A  + (size_t)a_in_row * 512 + gk);
            else          av = *(const float4*)(A2 + (size_t)a_in_row * 128 + (gk - 512));
        } else {
            av = *(const float4*)(A + (size_t)a_in_row * K + gk);
            if (MODE == 1 || MODE == 2) {
                float4 gm = *(const float4*)(gamma + gk);
                float4 bb = *(const float4*)(beta  + gk);
                av.x = (av.x - mean) * rstd * gm.x + bb.x;
                av.y = (av.y - mean) * rstd * gm.y + bb.y;
                av.z = (av.z - mean) * rstd * gm.z + bb.z;
                av.w = (av.w - mean) * rstd * gm.w + bb.w;
            }
        }
        As[akb + 0][arow] = av.x;
        As[akb + 1][arow] = av.y;
        As[akb + 2][arow] = av.z;
        As[akb + 3][arow] = av.w;

        float4 bv = *(const float4*)(W + (size_t)(n0 + arow) * K + gk);
        Bs[akb + 0][arow] = bv.x;
        Bs[akb + 1][arow] = bv.y;
        Bs[akb + 2][arow] = bv.z;
        Bs[akb + 3][arow] = bv.w;
        __syncthreads();

        #pragma unroll
        for (int kk = 0; kk < 16; kk++) {
            float4 a = *(const float4*)&As[kk][ty << 2];
            float4 b = *(const float4*)&Bs[kk][tx << 2];
            float ar[4] = {a.x, a.y, a.z, a.w};
            float br[4] = {b.x, b.y, b.z, b.w};
            #pragma unroll
            for (int i = 0; i < 4; i++)
                #pragma unroll
                for (int j = 0; j < 4; j++)
                    acc[i][j] += ar[i] * br[j];
        }
        __syncthreads();
    }

    #pragma unroll
    for (int i = 0; i < 4; i++) {
        int r = m0 + (ty << 2) + i;
        int orow = (MODE == 1) ? win_map(r) : r;
        #pragma unroll
        for (int j = 0; j < 4; j++) {
            int c = n0 + (tx << 2) + j;
            float y = acc[i][j] + bias[c];
            if (MODE == 0) {
                float sg = 1.f / (1.f + __expf(-y));
                float a = (c < 512) ? A[(size_t)r * 512 + c]
                                    : A2[(size_t)r * 128 + (c - 512)];
                C[(size_t)r * INCC + c] = a * sg;
            } else {
                C[(size_t)orow * N + c] = y;
            }
        }
    }
}

// ---------------- attention: one block per (b, window, head) ----------------
// Q[64,64], K[128,64] (64 local + 64 global), V[128,64]
#define ATTN_SMEM_FLOATS (64*68 + 64*132 + 128*68 + 64*132)   // 29952
#define ATTN_SMEM_BYTES  (ATTN_SMEM_FLOATS * 4)               // 119808

__global__ __launch_bounds__(256)
void attn_kernel(const float* __restrict__ Q, const float* __restrict__ Kl,
                 const float* __restrict__ Kg, const float* __restrict__ Vl,
                 const float* __restrict__ Vg, float* __restrict__ O) {
    extern __shared__ float smemf[];
    float* QsT = smemf;                  // [64 d][68]  (d-major)
    float* KsT = QsT + 64 * 68;          // [64 d][132] (d-major)
    float* Vs  = KsT + 64 * 132;         // [128 k][68]
    float* S   = Vs  + 128 * 68;         // [64 m][132]

    int bid = blockIdx.x;
    int b = bid >> 9;
    int rem = bid & 511;
    int g = rem >> 3;
    int h = rem & 7;

    size_t wbase = ((size_t)(b * GG + g) * NWIN) * DD + (size_t)h * DHH;
    size_t gbase = ((size_t)b * NGLOB) * DD + (size_t)h * DHH;
    const float* Qp  = Q  + wbase;
    const float* Klp = Kl + wbase;
    const float* Vlp = Vl + wbase;
    const float* Kgp = Kg + gbase;
    const float* Vgp = Vg + gbase;
    float* Op = O + wbase;

    int tid = threadIdx.x;

    // load Q (transposed, d-major)
    for (int e = tid; e < 64 * 16; e += 256) {
        int m = e >> 4, d4 = (e & 15) << 2;
        float4 v = *(const float4*)(Qp + (size_t)m * DD + d4);
        QsT[(d4 + 0) * 68 + m] = v.x;
        QsT[(d4 + 1) * 68 + m] = v.y;
        QsT[(d4 + 2) * 68 + m] = v.z;
        QsT[(d4 + 3) * 68 + m] = v.w;
    }
    // load K (transposed) and V (natural)
    for (int e = tid; e < 128 * 16; e += 256) {
        int kk = e >> 4, d4 = (e & 15) << 2;
        const float* ksrc = (kk < 64) ? (Klp + (size_t)kk * DD)
                                      : (Kgp + (size_t)(kk - 64) * DD);
        float4 v = *(const float4*)(ksrc + d4);
        KsT[(d4 + 0) * 132 + kk] = v.x;
        KsT[(d4 + 1) * 132 + kk] = v.y;
        KsT[(d4 + 2) * 132 + kk] = v.z;
        KsT[(d4 + 3) * 132 + kk] = v.w;
        const float* vsrc = (kk < 64) ? (Vlp + (size_t)kk * DD)
                                      : (Vgp + (size_t)(kk - 64) * DD);
        float4 w = *(const float4*)(vsrc + d4);
        *(float4*)&Vs[kk * 68 + d4] = w;
    }
    __syncthreads();

    int ty = tid >> 4, tx = tid & 15;

    // scores S[64,128] = Q @ K^T * 1/8
    {
        float acc[4][8];
        #pragma unroll
        for (int i = 0; i < 4; i++)
            #pragma unroll
            for (int j = 0; j < 8; j++) acc[i][j] = 0.f;
        #pragma unroll 4
        for (int d = 0; d < 64; d++) {
            float4 q  = *(const float4*)&QsT[d * 68 + (ty << 2)];
            float4 k0 = *(const float4*)&KsT[d * 132 + (tx << 3)];
            float4 k1 = *(const float4*)&KsT[d * 132 + (tx << 3) + 4];
            float qa[4] = {q.x, q.y, q.z, q.w};
            float kb[8] = {k0.x, k0.y, k0.z, k0.w, k1.x, k1.y, k1.z, k1.w};
            #pragma unroll
            for (int i = 0; i < 4; i++)
                #pragma unroll
                for (int j = 0; j < 8; j++)
                    acc[i][j] += qa[i] * kb[j];
        }
        #pragma unroll
        for (int i = 0; i < 4; i++)
            #pragma unroll
            for (int j = 0; j < 8; j++)
                S[((ty << 2) + i) * 132 + (tx << 3) + j] = acc[i][j] * 0.125f;
    }
    __syncthreads();

    // softmax per row (8 warps x 8 rows)
    {
        int warp = tid >> 5, lane = tid & 31;
        for (int m = warp; m < 64; m += 8) {
            float* sr = &S[m * 132];
            float v0 = sr[lane], v1 = sr[lane + 32], v2 = sr[lane + 64], v3 = sr[lane + 96];
            float mx = fmaxf(fmaxf(v0, v1), fmaxf(v2, v3));
            #pragma unroll
            for (int o = 16; o; o >>= 1) mx = fmaxf(mx, __shfl_xor_sync(0xffffffffu, mx, o));
            float e0 = __expf(v0 - mx), e1 = __expf(v1 - mx);
            float e2 = __expf(v2 - mx), e3 = __expf(v3 - mx);
            float s = e0 + e1 + e2 + e3;
            #pragma unroll
            for (int o = 16; o; o >>= 1) s += __shfl_xor_sync(0xffffffffu, s, o);
            float inv = 1.f / s;
            sr[lane]      = e0 * inv;
            sr[lane + 32] = e1 * inv;
            sr[lane + 64] = e2 * inv;
            sr[lane + 96] = e3 * inv;
        }
    }
    __syncthreads();

    // out[64,64] = P @ V
    {
        float acc[4][4];
        #pragma unroll
        for (int i = 0; i < 4; i++)
            #pragma unroll
            for (int j = 0; j < 4; j++) acc[i][j] = 0.f;
        for (int k = 0; k < 128; k++) {
            float4 vv = *(const float4*)&Vs[k * 68 + (tx << 2)];
            float vb[4] = {vv.x, vv.y, vv.z, vv.w};
            #pragma unroll
            for (int i = 0; i < 4; i++) {
                float p = S[((ty << 2) + i) * 132 + k];
                #pragma unroll
                for (int j = 0; j < 4; j++) acc[i][j] += p * vb[j];
            }
        }
        #pragma unroll
        for (int i = 0; i < 4; i++)
            #pragma unroll
            for (int j = 0; j < 4; j++)
                Op[(size_t)((ty << 2) + i) * DD + (tx << 2) + j] = acc[i][j];
    }
}

// ---------------- launch ----------------
extern "C" void kernel_launch(void* const* d_in, const int* in_sizes, int n_in,
                              void* d_out, int out_size) {
    const float* x       = (const float*)d_in[0];
    const float* f       = (const float*)d_in[1];
    const float* wq      = (const float*)d_in[2];
    const float* bq      = (const float*)d_in[3];
    const float* wk      = (const float*)d_in[4];
    const float* bk      = (const float*)d_in[5];
    const float* wv      = (const float*)d_in[6];
    const float* bv      = (const float*)d_in[7];
    const float* wo      = (const float*)d_in[8];
    const float* bo      = (const float*)d_in[9];
    const float* rw_w    = (const float*)d_in[10];
    const float* rw_b    = (const float*)d_in[11];
    const float* convk_w = (const float*)d_in[12];
    const float* convk_b = (const float*)d_in[13];
    const float* convv_w = (const float*)d_in[14];
    const float* convv_b = (const float*)d_in[15];
    const float* qn_g    = (const float*)d_in[16];
    const float* qn_b    = (const float*)d_in[17];
    const float* kn_g    = (const float*)d_in[18];
    const float* kn_b    = (const float*)d_in[19];
    const float* vn_g    = (const float*)d_in[20];
    const float* vn_b    = (const float*)d_in[21];
    float* out = (float*)d_out;

    float *qk, *kg, *vg, *Q, *Kl, *Vl, *Kg, *Vg, *O;
    float *st_qk, *st_x, *st_kg, *st_vg;
    cudaGetSymbolAddress((void**)&qk,    g_qk);
    cudaGetSymbolAddress((void**)&kg,    g_kg);
    cudaGetSymbolAddress((void**)&vg,    g_vg);
    cudaGetSymbolAddress((void**)&Q,     g_Q);
    cudaGetSymbolAddress((void**)&Kl,    g_Kl);
    cudaGetSymbolAddress((void**)&Vl,    g_Vl);
    cudaGetSymbolAddress((void**)&Kg,    g_Kg);
    cudaGetSymbolAddress((void**)&Vg,    g_Vg);
    cudaGetSymbolAddress((void**)&O,     g_O);
    cudaGetSymbolAddress((void**)&st_qk, g_st_qk);
    cudaGetSymbolAddress((void**)&st_x,  g_st_x);
    cudaGetSymbolAddress((void**)&st_kg, g_st_kg);
    cudaGetSymbolAddress((void**)&st_vg, g_st_vg);

    cudaFuncSetAttribute(attn_kernel, cudaFuncAttributeMaxDynamicSharedMemorySize,
                         ATTN_SMEM_BYTES);

    // 1) reweight: qk = concat(x,f) * sigmoid(concat @ rw_w^T + rw_b)
    gemm_kernel<0><<<dim3(10, 512), 256>>>(x, f, rw_w, rw_b,
                                           nullptr, nullptr, nullptr,
                                           qk, MTOK, INCC, INCC);
    // 2) independent: stats over x, dwconv of x -> vg
    ln_stats_kernel<<<MTOK, 256>>>(x, st_x, DD);
    dwconv_kernel<<<BT * GG, 256>>>(x, convv_w, convv_b, vg, DD);
    // 3) after reweight: stats over qk, dwconv of qk -> kg, then their stats
    ln_stats_kernel<<<MTOK, 256>>>(qk, st_qk, INCC);
    dwconv_kernel<<<BT * GG, 256>>>(qk, convk_w, convk_b, kg, INCC);
    ln_stats_kernel<<<BT * NGLOB, 256>>>(kg, st_kg, INCC);
    ln_stats_kernel<<<BT * NGLOB, 256>>>(vg, st_vg, DD);
    // 4) projections (LN fused into A loads)
    gemm_kernel<1><<<dim3(8, 512), 256>>>(qk, nullptr, wq, bq, st_qk, qn_g, qn_b,
                                          Q, MTOK, DD, INCC);
    gemm_kernel<1><<<dim3(8, 512), 256>>>(qk, nullptr, wk, bk, st_qk, kn_g, kn_b,
                                          Kl, MTOK, DD, INCC);
    gemm_kernel<2><<<dim3(8, 8), 256>>>(kg, nullptr, wk, bk, st_kg, kn_g, kn_b,
                                        Kg, BT * NGLOB, DD, INCC);
    gemm_kernel<1><<<dim3(8, 512), 256>>>(x, nullptr, wv, bv, st_x, vn_g, vn_b,
                                          Vl, MTOK, DD, DD);
    gemm_kernel<2><<<dim3(8, 8), 256>>>(vg, nullptr, wv, bv, st_vg, vn_g, vn_b,
                                        Vg, BT * NGLOB, DD, DD);
    // 5) attention per (b, window, head)
    attn_kernel<<<BT * GG * NHEAD, 256, ATTN_SMEM_BYTES>>>(Q, Kl, Kg, Vl, Vg, O);
    // 6) output projection with window-reverse gather
    gemm_kernel<3><<<dim3(8, 512), 256>>>(O, nullptr, wo, bo,
                                          nullptr, nullptr, nullptr,
                                          out, MTOK, DD, DD);
}

// round 3
// speedup vs baseline: 2.4571x; 2.4571x over previous
#include <cuda_runtime.h>
#include <cstdint>

// ---------------- arch-feature guard ----------------
#if defined(__CUDA_ARCH__) && (__CUDA_ARCH__ >= 1000) && \
    (defined(__CUDA_ARCH_FEAT_SM103_ALL) || defined(__CUDA_ARCH_FEAT_SM100_ALL) || \
     defined(__CUDA_ARCH_FEAT_SM101_ALL))
#define TC_PATH 1
#else
#define TC_PATH 0
#endif

// ---------------- problem constants ----------------
#define BT     8
#define NPIX   4096
#define DD     512
#define CFF    128
#define INCC   640
#define GG     64
#define NWIN   64
#define NGLOB  64
#define NHEAD  8
#define DHH    64
#define MTOK   32768

// ---------------- scratch ----------------
__device__ float g_qk [BT*NPIX*INCC];
__device__ float g_kg [BT*NGLOB*INCC];
__device__ float g_vg [BT*NGLOB*DD];
__device__ float g_Q  [BT*GG*NWIN*DD];
__device__ float g_Kl [BT*GG*NWIN*DD];
__device__ float g_Vl [BT*GG*NWIN*DD];
__device__ float g_Kg [BT*NGLOB*DD];
__device__ float g_Vg [BT*NGLOB*DD];
__device__ float g_O  [BT*GG*NWIN*DD];
__device__ float g_st_qk[MTOK*2];
__device__ float g_st_x [MTOK*2];
__device__ float g_st_kg[BT*NGLOB*2];
__device__ float g_st_vg[BT*NGLOB*2];

// ---------------- common helpers ----------------
__device__ __forceinline__ int win_map(int r) {
    int b = r >> 12;
    int p = r & 4095;
    int h = p >> 6, w = p & 63;
    int g = ((h >> 3) << 3) | (w >> 3);
    int n = ((h & 7) << 3) | (w & 7);
    return (((b << 6) | g) << 6) | n;
}

__device__ __forceinline__ float to_tf32(float x) {
    uint32_t u;
    asm("cvt.rna.tf32.f32 %0, %1;" : "=r"(u) : "f"(x));
    return __uint_as_float(u);
}
__device__ __forceinline__ float4 to_tf32_4(float4 v) {
    v.x = to_tf32(v.x); v.y = to_tf32(v.y);
    v.z = to_tf32(v.z); v.w = to_tf32(v.w);
    return v;
}

// mma.sync fallback primitive (sm_80+)
__device__ __forceinline__ void mma16n8k8(float* d, const uint32_t* a, const uint32_t* b) {
    asm volatile(
        "mma.sync.aligned.m16n8k8.row.col.f32.tf32.tf32.f32 "
        "{%0,%1,%2,%3}, {%4,%5,%6,%7}, {%8,%9}, {%0,%1,%2,%3};"
        : "+f"(d[0]), "+f"(d[1]), "+f"(d[2]), "+f"(d[3])
        : "r"(a[0]), "r"(a[1]), "r"(a[2]), "r"(a[3]), "r"(b[0]), "r"(b[1]));
}

#if TC_PATH
// ---------------- tcgen05 helpers (only compiled on arch-specific pass) ----------------
__device__ __forceinline__ uint32_t smem_u32(const void* p) {
    uint32_t a;
    asm("{ .reg .u64 t; cvta.to.shared.u64 t, %1; cvt.u32.u64 %0, t; }"
        : "=r"(a) : "l"(p));
    return a;
}
__device__ __forceinline__ uint32_t elect1() {
    uint32_t p;
    asm volatile("{ .reg .pred p; elect.sync _|p, 0xFFFFFFFF; selp.b32 %0,1,0,p; }"
                 : "=r"(p));
    return p;
}
#define MBARRIER_INIT(addr, cnt) \
    asm volatile("mbarrier.init.shared.b64 [%0], %1;" :: "r"(addr), "r"(cnt) : "memory")
#define MBARRIER_WAIT_PARITY(addr, par) do {                                     \
    uint32_t _m = (addr); uint32_t _p = (par); uint32_t _d;                      \
    asm volatile("{\n\t.reg .pred p;\n\t"                                        \
        "mbarrier.try_wait.parity.acquire.cta.shared::cta.b64 p, [%1], %2;\n\t"  \
        "selp.b32 %0, 1, 0, p;\n\t}"                                             \
        : "=r"(_d) : "r"(_m), "r"(_p) : "memory");                               \
    if (!_d) {                                                                   \
        asm volatile("{\n\t.reg .pred P1;\n\t"                                   \
        "WL_%=:\n\t"                                                             \
        "mbarrier.try_wait.parity.acquire.cta.shared::cta.b64 P1, [%0], %1, 0x989680;\n\t" \
        "@P1 bra.uni WD_%=;\n\t"                                                 \
        "bra.uni WL_%=;\n\t"                                                     \
        "WD_%=:\n\t}" :: "r"(_m), "r"(_p) : "memory");                           \
    }                                                                            \
} while (0)
#define TCGEN05_ALLOC(res, n) \
    asm volatile("tcgen05.alloc.cta_group::1.sync.aligned.shared::cta.b32 [%0], %1;" \
                 :: "r"(res), "r"((uint32_t)(n)) : "memory")
#define TCGEN05_RELINQ() \
    asm volatile("tcgen05.relinquish_alloc_permit.cta_group::1.sync.aligned;")
#define TCGEN05_DEALLOC(t, n) \
    asm volatile("tcgen05.dealloc.cta_group::1.sync.aligned.b32 %0, %1;" \
                 :: "r"(t), "r"((uint32_t)(n)))
#define TCGEN05_COMMIT(mb) \
    asm volatile("tcgen05.commit.cta_group::1.mbarrier::arrive::one.shared::cluster.b64 [%0];" \
                 :: "r"(mb) : "memory")
#define TCGEN05_WAIT_LD() asm volatile("tcgen05.wait::ld.sync.aligned;" ::: "memory")
#define TCGEN05_FENCE_AFTER() asm volatile("tcgen05.fence::after_thread_sync;" ::: "memory")
#define FENCE_ASYNC() asm volatile("fence.proxy.async.shared::cta;" ::: "memory")
#define TCGEN05_LD_X32(r, addr) \
    asm volatile( \
        "tcgen05.ld.sync.aligned.32x32b.x32.b32 " \
        "{%0, %1, %2, %3, %4, %5, %6, %7, " \
        " %8, %9, %10, %11, %12, %13, %14, %15, " \
        " %16, %17, %18, %19, %20, %21, %22, %23, " \
        " %24, %25, %26, %27, %28, %29, %30, %31}, [%32];" \
        : "=r"((r)[0]),  "=r"((r)[1]),  "=r"((r)[2]),  "=r"((r)[3]), \
          "=r"((r)[4]),  "=r"((r)[5]),  "=r"((r)[6]),  "=r"((r)[7]), \
          "=r"((r)[8]),  "=r"((r)[9]),  "=r"((r)[10]), "=r"((r)[11]), \
          "=r"((r)[12]), "=r"((r)[13]), "=r"((r)[14]), "=r"((r)[15]), \
          "=r"((r)[16]), "=r"((r)[17]), "=r"((r)[18]), "=r"((r)[19]), \
          "=r"((r)[20]), "=r"((r)[21]), "=r"((r)[22]), "=r"((r)[23]), \
          "=r"((r)[24]), "=r"((r)[25]), "=r"((r)[26]), "=r"((r)[27]), \
          "=r"((r)[28]), "=r"((r)[29]), "=r"((r)[30]), "=r"((r)[31]) \
        : "r"(addr))

static __device__ __forceinline__ uint64_t make_desc(uint32_t addr) {
    const uint64_t base =
        (uint64_t(2) << 61) | (uint64_t(1) << 46) | (uint64_t(64) << 32) | (uint64_t(1) << 16);
    return base | ((uint64_t)(addr >> 4) & 0x3FFF);
}
__device__ __forceinline__ void mma_tf32_ss(uint32_t d, uint64_t ad, uint64_t bd,
                                            uint32_t idesc, uint32_t acc) {
    asm volatile(
        "{\n\t.reg .pred p;\n\tsetp.ne.u32 p, %5, 0;\n\t"
        "tcgen05.mma.cta_group::1.kind::tf32 [%0], %1, %2, %3, {%4,%4,%4,%4}, p;\n\t}"
        :: "r"(d), "l"(ad), "l"(bd), "r"(idesc), "r"(0u), "r"(acc) : "memory");
}
#endif  // TC_PATH

// ---------------- LayerNorm stats: one warp per row ----------------
__global__ __launch_bounds__(256)
void ln_stats_kernel(const float* __restrict__ X, float* __restrict__ stats, int K) {
    int row = blockIdx.x * 8 + (threadIdx.x >> 5);
    int lane = threadIdx.x & 31;
    const float* xr = X + (size_t)row * K;
    float s = 0.f, ss = 0.f;
    for (int k = lane * 4; k < K; k += 128) {
        float4 v = *(const float4*)(xr + k);
        s  += v.x + v.y + v.z + v.w;
        ss += v.x * v.x + v.y * v.y + v.z * v.z + v.w * v.w;
    }
    #pragma unroll
    for (int o = 16; o; o >>= 1) {
        s  += __shfl_xor_sync(0xffffffffu, s, o);
        ss += __shfl_xor_sync(0xffffffffu, ss, o);
    }
    if (lane == 0) {
        float mean = s / K;
        float var = ss / K - mean * mean;
        float2 st = make_float2(mean, rsqrtf(var + 1e-5f));
        *(float2*)(stats + (size_t)row * 2) = st;
    }
}

// ---------------- depthwise 8x8 stride-8 conv ----------------
__global__ __launch_bounds__(256)
void dwconv_kernel(const float* __restrict__ X, const float* __restrict__ Wc,
                   const float* __restrict__ bc, float* __restrict__ out, int C) {
    int bw = blockIdx.x;
    int b = bw >> 6;
    int g = bw & 63;
    int gh = g >> 3, gw = g & 7;
    const float* xb = X + (size_t)b * NPIX * C;
    for (int c = threadIdx.x; c < C; c += 256) {
        float s = bc[c];
        #pragma unroll
        for (int i = 0; i < 8; i++)
            #pragma unroll
            for (int j = 0; j < 8; j++)
                s += xb[(size_t)((gh * 8 + i) * 64 + (gw * 8 + j)) * C + c]
                     * Wc[c * 64 + i * 8 + j];
        out[(size_t)bw * C + c] = s;
    }
}

// ---------------- GEMM: C[M,N] = op(A)[M,K] @ W[N,K]^T ----------------
// MODE 0: A split (x|f); out = a * sigmoid(acc+bias); spatial write
// MODE 1: LN-fused A; +bias; output row = win_map
// MODE 2: LN-fused A; +bias; identity rows
// MODE 3: A gathered via win_map; +bias; spatial write
template<int MODE, int NT>
__global__ __launch_bounds__(256)
void mma_gemm(const float* __restrict__ A, const float* __restrict__ A2,
              const float* __restrict__ W, const float* __restrict__ bias,
              const float* __restrict__ stats, const float* __restrict__ gamma,
              const float* __restrict__ beta, float* __restrict__ C,
              int M, int N, int K) {
#if TC_PATH
    // ================= tcgen05 TF32 SS pipeline =================
    extern __shared__ char smem_raw[];
    char* p1k = (char*)((((uintptr_t)smem_raw) + 1023) & ~(uintptr_t)1023);
    const uint32_t base = smem_u32(p1k);
    const uint32_t tmem_ptr_addr = base;
    const uint32_t mb0 = base + 16, mb1 = base + 24;
    char* At[2] = { p1k + 1024, p1k + 1024 + 16384 };
    char* Bt[2] = { p1k + 1024 + 32768, p1k + 1024 + 32768 + NT * 128 };

    const int tid = threadIdx.x;
    const int wid = tid >> 5;
    const int m0 = blockIdx.y * 128;
    const int n0 = blockIdx.x * NT;
    const int NC = K >> 5;
    const int q = tid & 7;

    if (tid == 0) { MBARRIER_INIT(mb0, 1); MBARRIER_INIT(mb1, 1); }
    if (wid == 0) { TCGEN05_ALLOC(tmem_ptr_addr, NT); TCGEN05_RELINQ(); }
    __syncthreads();
    uint32_t tmem;
    asm volatile("ld.shared.b32 %0, [%1];" : "=r"(tmem) : "r"(tmem_ptr_addr));

    int arow[4]; float mean[4], rstd[4];
    #pragma unroll
    for (int i = 0; i < 4; i++) {
        int r = m0 + (tid >> 3) + i * 32;
        arow[i] = (MODE == 3) ? win_map(r) : r;
        if (MODE == 1 || MODE == 2) {
            float2 st = *(const float2*)(stats + (size_t)r * 2);
            mean[i] = st.x; rstd[i] = st.y;
        }
    }

    auto load_chunk = [&](int c, int buf) {
        int k0 = c << 5;
        int gk = k0 + q * 4;
        #pragma unroll
        for (int i = 0; i < 4; i++) {
            float4 av;
            if (MODE == 0) {
                if (k0 < 512) av = *(const float4*)(A  + (size_t)arow[i] * 512 + gk);
                else          av = *(const float4*)(A2 + (size_t)arow[i] * 128 + (gk - 512));
            } else {
                av = *(const float4*)(A + (size_t)arow[i] * K + gk);
                if (MODE == 1 || MODE == 2) {
                    float4 gm = *(const float4*)(gamma + gk);
                    float4 bb = *(const float4*)(beta  + gk);
                    av.x = (av.x - mean[i]) * rstd[i] * gm.x + bb.x;
                    av.y = (av.y - mean[i]) * rstd[i] * gm.y + bb.y;
                    av.z = (av.z - mean[i]) * rstd[i] * gm.z + bb.z;
                    av.w = (av.w - mean[i]) * rstd[i] * gm.w + bb.w;
                }
            }
            av = to_tf32_4(av);
            uint32_t off = (uint32_t)(((tid >> 3) + i * 32) << 7) + (q << 4);
            off ^= (off >> 3) & 0x70;
            *(float4*)(At[buf] + off) = av;
        }
        #pragma unroll
        for (int i = 0; i < NT * 8 / 256; i++) {
            int row = (tid >> 3) + i * 32;
            float4 bv = *(const float4*)(W + (size_t)(n0 + row) * K + gk);
            bv = to_tf32_4(bv);
            uint32_t off = (uint32_t)(row << 7) + (q << 4);
            off ^= (off >> 3) & 0x70;
            *(float4*)(Bt[buf] + off) = bv;
        }
    };

    load_chunk(0, 0);
    if (NC > 1) load_chunk(1, 1);
    FENCE_ASYNC();
    __syncthreads();

    const uint32_t idesc = (1u << 4) | (2u << 7) | (2u << 10)
                         | ((uint32_t)(NT / 8) << 17) | (8u << 24);

    for (int c = 0; c < NC; c++) {
        int buf = c & 1;
        uint32_t mb = buf ? mb1 : mb0;
        if (wid == 0) {
            if (elect1()) {
                uint64_t ad = make_desc(smem_u32(At[buf]));
                uint64_t bd = make_desc(smem_u32(Bt[buf]));
                #pragma unroll
                for (int s = 0; s < 4; s++)
                    mma_tf32_ss(tmem, ad + s * 2, bd + s * 2, idesc,
                                (uint32_t)((c > 0) | (s > 0)));
                TCGEN05_COMMIT(mb);
            }
        }
        int nc = c + 2;
        if (nc < NC) {
            MBARRIER_WAIT_PARITY(mb, (uint32_t)((c >> 1) & 1));
            load_chunk(nc, buf);
            FENCE_ASYNC();
        }
        __syncthreads();
    }
    {
        int lc = NC - 1;
        uint32_t mb = (lc & 1) ? mb1 : mb0;
        MBARRIER_WAIT_PARITY(mb, (uint32_t)((lc >> 1) & 1));
    }
    TCGEN05_FENCE_AFTER();

    if (tid < 128) {
        int r = m0 + tid;
        size_t orow = (MODE == 1) ? (size_t)win_map(r) : (size_t)r;
        float* crow = C + orow * (size_t)N;
        #pragma unroll
        for (int cb = 0; cb < NT; cb += 32) {
            uint32_t dr[32];
            TCGEN05_LD_X32(dr, tmem + cb);
            TCGEN05_WAIT_LD();
            #pragma unroll
            for (int j = 0; j < 32; j += 4) {
                int c = n0 + cb + j;
                float4 o;
                o.x = __uint_as_float(dr[j + 0]) + bias[c + 0];
                o.y = __uint_as_float(dr[j + 1]) + bias[c + 1];
                o.z = __uint_as_float(dr[j + 2]) + bias[c + 2];
                o.w = __uint_as_float(dr[j + 3]) + bias[c + 3];
                if (MODE == 0) {
                    float4 a = (c < 512)
                        ? *(const float4*)(A  + (size_t)r * 512 + c)
                        : *(const float4*)(A2 + (size_t)r * 128 + (c - 512));
                    o.x = a.x / (1.f + __expf(-o.x));
                    o.y = a.y / (1.f + __expf(-o.y));
                    o.z = a.z / (1.f + __expf(-o.z));
                    o.w = a.w / (1.f + __expf(-o.w));
                }
                *(float4*)(crow + c) = o;
            }
        }
    }
    __syncthreads();
    if (wid == 0) TCGEN05_DEALLOC(tmem, NT);

#else
    // ================= mma.sync.m16n8k8 tf32 fallback =================
    extern __shared__ char smem_raw[];
    float* As = (float*)smem_raw;          // [128][36]
    float* Bs = As + 128 * 36;             // [128][36]

    const int tid = threadIdx.x;
    const int m0 = blockIdx.y * 128;
    const int n0 = blockIdx.x * NT;
    const int q = tid & 7;
    const int lane = tid & 31, grp = lane >> 2, tig = lane & 3;
    const int w = tid >> 5, mblk = (w & 3) * 32, nblk = (w >> 2) * 64;
    const int NC = K >> 5;

    int arow[4]; float mean[4], rstd[4];
    #pragma unroll
    for (int i = 0; i < 4; i++) {
        int r = m0 + (tid >> 3) + i * 32;
        arow[i] = (MODE == 3) ? win_map(r) : r;
        if (MODE == 1 || MODE == 2) {
            float2 st = *(const float2*)(stats + (size_t)r * 2);
            mean[i] = st.x; rstd[i] = st.y;
        }
    }

    #pragma unroll
    for (int half = 0; half < NT / 128; half++) {
        float acc[2][8][4];
        #pragma unroll
        for (int mt = 0; mt < 2; mt++)
            #pragma unroll
            for (int nt = 0; nt < 8; nt++)
                #pragma unroll
                for (int e = 0; e < 4; e++) acc[mt][nt][e] = 0.f;

        for (int ch = 0; ch < NC; ch++) {
            int k0g = ch << 5;
            int gk = k0g + q * 4;
            // load A chunk 128x32
            #pragma unroll
            for (int i = 0; i < 4; i++) {
                float4 av;
                if (MODE == 0) {
                    if (k0g < 512) av = *(const float4*)(A  + (size_t)arow[i] * 512 + gk);
                    else           av = *(const float4*)(A2 + (size_t)arow[i] * 128 + (gk - 512));
                } else {
                    av = *(const float4*)(A + (size_t)arow[i] * K + gk);
                    if (MODE == 1 || MODE == 2) {
                        float4 gm = *(const float4*)(gamma + gk);
                        float4 bb = *(const float4*)(beta  + gk);
                        av.x = (av.x - mean[i]) * rstd[i] * gm.x + bb.x;
                        av.y = (av.y - mean[i]) * rstd[i] * gm.y + bb.y;
                        av.z = (av.z - mean[i]) * rstd[i] * gm.z + bb.z;
                        av.w = (av.w - mean[i]) * rstd[i] * gm.w + bb.w;
                    }
                }
                av = to_tf32_4(av);
                *(float4*)&As[((tid >> 3) + i * 32) * 36 + q * 4] = av;
            }
            // load B half-chunk 128x32
            #pragma unroll
            for (int i = 0; i < 4; i++) {
                int row = (tid >> 3) + i * 32;
                float4 bv = *(const float4*)(W + (size_t)(n0 + half * 128 + row) * K + gk);
                bv = to_tf32_4(bv);
                *(float4*)&Bs[row * 36 + q * 4] = bv;
            }
            __syncthreads();

            #pragma unroll
            for (int k8 = 0; k8 < 4; k8++) {
                int k0 = k8 * 8;
                uint32_t af[2][4];
                #pragma unroll
                for (int mt = 0; mt < 2; mt++) {
                    int rb = mblk + mt * 16;
                    af[mt][0] = __float_as_uint(As[(rb + grp)     * 36 + k0 + tig]);
                    af[mt][1] = __float_as_uint(As[(rb + grp + 8) * 36 + k0 + tig]);
                    af[mt][2] = __float_as_uint(As[(rb + grp)     * 36 + k0 + tig + 4]);
                    af[mt][3] = __float_as_uint(As[(rb + grp + 8) * 36 + k0 + tig + 4]);
                }
                #pragma unroll
                for (int nt = 0; nt < 8; nt++) {
                    uint32_t bf[2];
                    int nb = nblk + nt * 8 + grp;
                    bf[0] = __float_as_uint(Bs[nb * 36 + k0 + tig]);
                    bf[1] = __float_as_uint(Bs[nb * 36 + k0 + tig + 4]);
                    mma16n8k8(acc[0][nt], af[0], bf);
                    mma16n8k8(acc[1][nt], af[1], bf);
                }
            }
            __syncthreads();
        }

        // epilogue from register fragments
        #pragma unroll
        for (int mt = 0; mt < 2; mt++) {
            #pragma unroll
            for (int hr = 0; hr < 2; hr++) {
                int r = m0 + mblk + mt * 16 + grp + hr * 8;
                size_t orow = (MODE == 1) ? (size_t)win_map(r) : (size_t)r;
                float* crow = C + orow * (size_t)N;
                #pragma unroll
                for (int nt = 0; nt < 8; nt++) {
                    int cc = n0 + half * 128 + nblk + nt * 8 + 2 * tig;
                    float y0 = acc[mt][nt][hr * 2 + 0] + bias[cc];
                    float y1 = acc[mt][nt][hr * 2 + 1] + bias[cc + 1];
                    if (MODE == 0) {
                        float a0 = (cc < 512) ? A[(size_t)r * 512 + cc]
                                              : A2[(size_t)r * 128 + (cc - 512)];
                        float a1 = (cc + 1 < 512) ? A[(size_t)r * 512 + cc + 1]
                                                  : A2[(size_t)r * 128 + (cc + 1 - 512)];
                        y0 = a0 / (1.f + __expf(-y0));
                        y1 = a1 / (1.f + __expf(-y1));
                    }
                    float2 o = make_float2(y0, y1);
                    *(float2*)(crow + cc) = o;
                }
            }
        }
    }
#endif
}

// ---------------- attention ----------------
#define ATTN_SMEM_FLOATS (64*68 + 64*132 + 128*68 + 64*132)
#define ATTN_SMEM_BYTES  (ATTN_SMEM_FLOATS * 4)

__global__ __launch_bounds__(256)
void attn_kernel(const float* __restrict__ Q, const float* __restrict__ Kl,
                 const float* __restrict__ Kg, const float* __restrict__ Vl,
                 const float* __restrict__ Vg, float* __restrict__ O) {
    extern __shared__ float smemf[];
    float* QsT = smemf;
    float* KsT = QsT + 64 * 68;
    float* Vs  = KsT + 64 * 132;
    float* S   = Vs  + 128 * 68;

    int bid = blockIdx.x;
    int b = bid >> 9;
    int rem = bid & 511;
    int g = rem >> 3;
    int h = rem & 7;

    size_t wbase = ((size_t)(b * GG + g) * NWIN) * DD + (size_t)h * DHH;
    size_t gbase = ((size_t)b * NGLOB) * DD + (size_t)h * DHH;
    const float* Qp  = Q  + wbase;
    const float* Klp = Kl + wbase;
    const float* Vlp = Vl + wbase;
    const float* Kgp = Kg + gbase;
    const float* Vgp = Vg + gbase;
    float* Op = O + wbase;

    int tid = threadIdx.x;

    for (int e = tid; e < 64 * 16; e += 256) {
        int m = e >> 4, d4 = (e & 15) << 2;
        float4 v = *(const float4*)(Qp + (size_t)m * DD + d4);
        QsT[(d4 + 0) * 68 + m] = v.x;
        QsT[(d4 + 1) * 68 + m] = v.y;
        QsT[(d4 + 2) * 68 + m] = v.z;
        QsT[(d4 + 3) * 68 + m] = v.w;
    }
    for (int e = tid; e < 128 * 16; e += 256) {
        int kk = e >> 4, d4 = (e & 15) << 2;
        const float* ksrc = (kk < 64) ? (Klp + (size_t)kk * DD)
                                      : (Kgp + (size_t)(kk - 64) * DD);
        float4 v = *(const float4*)(ksrc + d4);
        KsT[(d4 + 0) * 132 + kk] = v.x;
        KsT[(d4 + 1) * 132 + kk] = v.y;
        KsT[(d4 + 2) * 132 + kk] = v.z;
        KsT[(d4 + 3) * 132 + kk] = v.w;
        const float* vsrc = (kk < 64) ? (Vlp + (size_t)kk * DD)
                                      : (Vgp + (size_t)(kk - 64) * DD);
        float4 wv = *(const float4*)(vsrc + d4);
        *(float4*)&Vs[kk * 68 + d4] = wv;
    }
    __syncthreads();

    int ty = tid >> 4, tx = tid & 15;

    {
        float acc[4][8];
        #pragma unroll
        for (int i = 0; i < 4; i++)
            #pragma unroll
            for (int j = 0; j < 8; j++) acc[i][j] = 0.f;
        #pragma unroll 4
        for (int d = 0; d < 64; d++) {
            float4 qv = *(const float4*)&QsT[d * 68 + (ty << 2)];
            float4 k0 = *(const float4*)&KsT[d * 132 + (tx << 3)];
            float4 k1 = *(const float4*)&KsT[d * 132 + (tx << 3) + 4];
            float qa[4] = {qv.x, qv.y, qv.z, qv.w};
            float kb[8] = {k0.x, k0.y, k0.z, k0.w, k1.x, k1.y, k1.z, k1.w};
            #pragma unroll
            for (int i = 0; i < 4; i++)
                #pragma unroll
                for (int j = 0; j < 8; j++)
                    acc[i][j] += qa[i] * kb[j];
        }
        #pragma unroll
        for (int i = 0; i < 4; i++)
            #pragma unroll
            for (int j = 0; j < 8; j++)
                S[((ty << 2) + i) * 132 + (tx << 3) + j] = acc[i][j] * 0.125f;
    }
    __syncthreads();

    {
        int warp = tid >> 5, lane = tid & 31;
        for (int m = warp; m < 64; m += 8) {
            float* sr = &S[m * 132];
            float v0 = sr[lane], v1 = sr[lane + 32], v2 = sr[lane + 64], v3 = sr[lane + 96];
            float mx = fmaxf(fmaxf(v0, v1), fmaxf(v2, v3));
            #pragma unroll
            for (int o = 16; o; o >>= 1) mx = fmaxf(mx, __shfl_xor_sync(0xffffffffu, mx, o));
            float e0 = __expf(v0 - mx), e1 = __expf(v1 - mx);
            float e2 = __expf(v2 - mx), e3 = __expf(v3 - mx);
            float s = e0 + e1 + e2 + e3;
            #pragma unroll
            for (int o = 16; o; o >>= 1) s += __shfl_xor_sync(0xffffffffu, s, o);
            float inv = 1.f / s;
            sr[lane]      = e0 * inv;
            sr[lane + 32] = e1 * inv;
            sr[lane + 64] = e2 * inv;
            sr[lane + 96] = e3 * inv;
        }
    }
    __syncthreads();

    {
        float acc[4][4];
        #pragma unroll
        for (int i = 0; i < 4; i++)
            #pragma unroll
            for (int j = 0; j < 4; j++) acc[i][j] = 0.f;
        for (int k = 0; k < 128; k++) {
            float4 vv = *(const float4*)&Vs[k * 68 + (tx << 2)];
            float vb[4] = {vv.x, vv.y, vv.z, vv.w};
            #pragma unroll
            for (int i = 0; i < 4; i++) {
                float p = S[((ty << 2) + i) * 132 + k];
                #pragma unroll
                for (int j = 0; j < 4; j++) acc[i][j] += p * vb[j];
            }
        }
        #pragma unroll
        for (int i = 0; i < 4; i++)
            #pragma unroll
            for (int j = 0; j < 4; j++)
                Op[(size_t)((ty << 2) + i) * DD + (tx << 2) + j] = acc[i][j];
    }
}

// ---------------- launch ----------------
#define SMEM_G128 (2048 + 32768 + 2 * 128 * 128)   // 67584
#define SMEM_G256 (2048 + 32768 + 2 * 256 * 128)   // 100352

extern "C" void kernel_launch(void* const* d_in, const int* in_sizes, int n_in,
                              void* d_out, int out_size) {
    const float* x       = (const float*)d_in[0];
    const float* f       = (const float*)d_in[1];
    const float* wq      = (const float*)d_in[2];
    const float* bq      = (const float*)d_in[3];
    const float* wk      = (const float*)d_in[4];
    const float* bk      = (const float*)d_in[5];
    const float* wv      = (const float*)d_in[6];
    const float* bv      = (const float*)d_in[7];
    const float* wo      = (const float*)d_in[8];
    const float* bo      = (const float*)d_in[9];
    const float* rw_w    = (const float*)d_in[10];
    const float* rw_b    = (const float*)d_in[11];
    const float* convk_w = (const float*)d_in[12];
    const float* convk_b = (const float*)d_in[13];
    const float* convv_w = (const float*)d_in[14];
    const float* convv_b = (const float*)d_in[15];
    const float* qn_g    = (const float*)d_in[16];
    const float* qn_b    = (const float*)d_in[17];
    const float* kn_g    = (const float*)d_in[18];
    const float* kn_b    = (const float*)d_in[19];
    const float* vn_g    = (const float*)d_in[20];
    const float* vn_b    = (const float*)d_in[21];
    float* out = (float*)d_out;

    float *qk, *kg, *vg, *Q, *Kl, *Vl, *Kg, *Vg, *O;
    float *st_qk, *st_x, *st_kg, *st_vg;
    cudaGetSymbolAddress((void**)&qk,    g_qk);
    cudaGetSymbolAddress((void**)&kg,    g_kg);
    cudaGetSymbolAddress((void**)&vg,    g_vg);
    cudaGetSymbolAddress((void**)&Q,     g_Q);
    cudaGetSymbolAddress((void**)&Kl,    g_Kl);
    cudaGetSymbolAddress((void**)&Vl,    g_Vl);
    cudaGetSymbolAddress((void**)&Kg,    g_Kg);
    cudaGetSymbolAddress((void**)&Vg,    g_Vg);
    cudaGetSymbolAddress((void**)&O,     g_O);
    cudaGetSymbolAddress((void**)&st_qk, g_st_qk);
    cudaGetSymbolAddress((void**)&st_x,  g_st_x);
    cudaGetSymbolAddress((void**)&st_kg, g_st_kg);
    cudaGetSymbolAddress((void**)&st_vg, g_st_vg);

    cudaFuncSetAttribute(attn_kernel, cudaFuncAttributeMaxDynamicSharedMemorySize,
                         ATTN_SMEM_BYTES);
    cudaFuncSetAttribute(mma_gemm<0,128>, cudaFuncAttributeMaxDynamicSharedMemorySize,
                         SMEM_G128);
    cudaFuncSetAttribute(mma_gemm<1,256>, cudaFuncAttributeMaxDynamicSharedMemorySize,
                         SMEM_G256);
    cudaFuncSetAttribute(mma_gemm<2,256>, cudaFuncAttributeMaxDynamicSharedMemorySize,
                         SMEM_G256);
    cudaFuncSetAttribute(mma_gemm<3,256>, cudaFuncAttributeMaxDynamicSharedMemorySize,
                         SMEM_G256);

    // 1) reweight GEMM
    mma_gemm<0,128><<<dim3(5, 256), 256, SMEM_G128>>>(
        x, f, rw_w, rw_b, nullptr, nullptr, nullptr, qk, MTOK, INCC, INCC);
    // 2) independent
    ln_stats_kernel<<<MTOK / 8, 256>>>(x, st_x, DD);
    dwconv_kernel<<<BT * GG, 256>>>(x, convv_w, convv_b, vg, DD);
    // 3) after reweight
    ln_stats_kernel<<<MTOK / 8, 256>>>(qk, st_qk, INCC);
    dwconv_kernel<<<BT * GG, 256>>>(qk, convk_w, convk_b, kg, INCC);
    ln_stats_kernel<<<(BT * NGLOB) / 8, 256>>>(kg, st_kg, INCC);
    ln_stats_kernel<<<(BT * NGLOB) / 8, 256>>>(vg, st_vg, DD);
    // 4) projections
    mma_gemm<1,256><<<dim3(2, 256), 256, SMEM_G256>>>(
        qk, nullptr, wq, bq, st_qk, qn_g, qn_b, Q, MTOK, DD, INCC);
    mma_gemm<1,256><<<dim3(2, 256), 256, SMEM_G256>>>(
        qk, nullptr, wk, bk, st_qk, kn_g, kn_b, Kl, MTOK, DD, INCC);
    mma_gemm<2,256><<<dim3(2, 4), 256, SMEM_G256>>>(
        kg, nullptr, wk, bk, st_kg, kn_g, kn_b, Kg, BT * NGLOB, DD, INCC);
    mma_gemm<1,256><<<dim3(2, 256), 256, SMEM_G256>>>(
        x, nullptr, wv, bv, st_x, vn_g, vn_b, Vl, MTOK, DD, DD);
    mma_gemm<2,256><<<dim3(2, 4), 256, SMEM_G256>>>(
        vg, nullptr, wv, bv, st_vg, vn_g, vn_b, Vg, BT * NGLOB, DD, DD);
    // 5) attention
    attn_kernel<<<BT * GG * NHEAD, 256, ATTN_SMEM_BYTES>>>(Q, Kl, Kg, Vl, Vg, O);
    // 6) out projection
    mma_gemm<3,256><<<dim3(2, 256), 256, SMEM_G256>>>(
        O, nullptr, wo, bo, nullptr, nullptr, nullptr, out, MTOK, DD, DD);
}